// round 9
// baseline (speedup 1.0000x reference)
#include <cuda_runtime.h>
#include <cuda_fp16.h>
#include <cstdint>

// LNLieBracketChannelMix via single-term fp16 mma.sync (fp32 accumulate).
// R8: GT 64->128 (CTA = 128g x 96cols, warp tile 32x96) to amortize
//     LDG/STS/LDSM traffic over 2x MMA work. 1 CTA/SM, 8 warps.

#define B_    8
#define F_    256
#define NDIM  4096
#define COLS  12288
#define GT    128
#define NT    32
#define CT    96
#define KC    32
#define NCH   8
#define THREADS 256

#define A_STRIDE 80                 // 32 fp16 = 64B + 16B pad
#define B_STRIDE 208                // 96 fp16 = 192B + 16B pad
#define A_PART   (GT * A_STRIDE)    // 10240 (one W tile, 128 rows)
#define B_OFF    (2 * A_PART)       // 20480
#define B_PART   (KC * B_STRIDE)    // 6656
#define STAGE    (B_OFF + B_PART)   // 27136
#define SMEM_TOTAL (2 * GT * CT * 4)  // 98304 (epilogue D1/D2 > 2*STAGE=54272)

static __device__ __forceinline__ uint32_t s2u(const void* p) {
    uint32_t a;
    asm("{ .reg .u64 t; cvta.to.shared.u64 t, %1; cvt.u32.u64 %0, t; }" : "=r"(a) : "l"(p));
    return a;
}
static __device__ __forceinline__ void lm4(uint32_t* r, uint32_t a) {
    asm volatile("ldmatrix.sync.aligned.m8n8.x4.shared.b16 {%0,%1,%2,%3}, [%4];"
        : "=r"(r[0]), "=r"(r[1]), "=r"(r[2]), "=r"(r[3]) : "r"(a));
}
static __device__ __forceinline__ void lm4t(uint32_t* r, uint32_t a) {
    asm volatile("ldmatrix.sync.aligned.m8n8.x4.trans.shared.b16 {%0,%1,%2,%3}, [%4];"
        : "=r"(r[0]), "=r"(r[1]), "=r"(r[2]), "=r"(r[3]) : "r"(a));
}
static __device__ __forceinline__ void mma(float* d, const uint32_t* a, uint32_t b0, uint32_t b1) {
    asm volatile(
        "mma.sync.aligned.m16n8k16.row.col.f32.f16.f16.f32 "
        "{%0,%1,%2,%3}, {%4,%5,%6,%7}, {%8,%9}, {%0,%1,%2,%3};"
        : "+f"(d[0]), "+f"(d[1]), "+f"(d[2]), "+f"(d[3])
        : "r"(a[0]), "r"(a[1]), "r"(a[2]), "r"(a[3]), "r"(b0), "r"(b1));
}
static __device__ __forceinline__ uint2 cvt4h(float4 v) {
    __half2 a = __floats2half2_rn(v.x, v.y);
    __half2 b = __floats2half2_rn(v.z, v.w);
    uint2 r;
    r.x = *reinterpret_cast<uint32_t*>(&a);
    r.y = *reinterpret_cast<uint32_t*>(&b);
    return r;
}

__global__ __launch_bounds__(THREADS, 1)
void lnlb_f16_kernel(const float* __restrict__ x,
                     const float* __restrict__ M1,
                     const float* __restrict__ M2,
                     const float* __restrict__ W1,
                     const float* __restrict__ W2,
                     float* __restrict__ out)
{
    extern __shared__ char smem[];
    const uint32_t sb = s2u(smem);

    const int tid = threadIdx.x;
    const int warp = tid >> 5, lane = tid & 31;
    const int n0 = blockIdx.x * NT;
    const int g0 = blockIdx.y * GT;
    const int b  = blockIdx.z;
    const float* xb = x + (size_t)b * F_ * COLS;

    const int mat = warp >> 2;           // 0 -> W1/D1, 1 -> W2/D2
    const int wg  = (warp & 3) * 32;     // g-strip within 128

    float acc[2][12][4];                 // 2 m-frags x 12 n8-frags
    #pragma unroll
    for (int m = 0; m < 2; m++)
        #pragma unroll
        for (int t = 0; t < 12; t++)
            #pragma unroll
            for (int j = 0; j < 4; j++) acc[m][t][j] = 0.f;

    const int lrow = lane & 15;
    const uint32_t lhA = (lane & 16) ? 16u : 0u;
    const uint32_t lhB = (lane & 16) ? 8u  : 0u;
    uint32_t aoff[2], boff[6];
    #pragma unroll
    for (int m = 0; m < 2; m++) aoff[m] = (uint32_t)((wg + 16 * m + lrow) * A_STRIDE) + lhA;
    #pragma unroll
    for (int t = 0; t < 6; t++) boff[t] = (uint32_t)(lrow * B_STRIDE + (t * 16 + lhB) * 2);
    const uint32_t aBase = (uint32_t)(mat * A_PART);

    // register-pipelined staging: LDG chunk into regs, later cvt+STS
    float4 ra[8], rb[3];
    auto ldchunk = [&](int c) {
        const int f0 = c * KC;
        #pragma unroll
        for (int j = 0; j < 8; j++) {          // A: 2 W tiles x 128 g x 8 f-quads
            int i = tid + j * THREADS;
            int t = i >> 10, r = i & 1023, g = r >> 3, fq = r & 7;
            ra[j] = *(const float4*)((t ? W2 : W1) + (g0 + g) * F_ + f0 + fq * 4);
        }
        #pragma unroll
        for (int j = 0; j < 3; j++) {          // B: 32 f x 24 col-quads
            int i = tid + j * THREADS;
            int f = i / 24, cq = i % 24;
            rb[j] = *(const float4*)(xb + (size_t)(f0 + f) * COLS + (cq >> 3) * NDIM + n0 + (cq & 7) * 4);
        }
    };
    auto stchunk = [&](char* buf) {
        #pragma unroll
        for (int j = 0; j < 8; j++) {
            int i = tid + j * THREADS;
            int t = i >> 10, r = i & 1023, g = r >> 3, fq = r & 7;
            *(uint2*)(buf + t * A_PART + g * A_STRIDE + fq * 8) = cvt4h(ra[j]);
        }
        #pragma unroll
        for (int j = 0; j < 3; j++) {
            int i = tid + j * THREADS;
            int f = i / 24, cq = i % 24;
            *(uint2*)(buf + B_OFF + f * B_STRIDE + cq * 8) = cvt4h(rb[j]);
        }
    };

    ldchunk(0);
    stchunk(smem);
    __syncthreads();

    for (int c = 0; c < NCH; ++c) {
        if (c + 1 < NCH) ldchunk(c + 1);          // LDGs in flight over MMA block

        const uint32_t bu = sb + (uint32_t)((c & 1) * STAGE);
        #pragma unroll
        for (int ks2 = 0; ks2 < 2; ++ks2) {
            const uint32_t ksA = ks2 * 32;
            const uint32_t ksB = ks2 * 16 * B_STRIDE;

            uint32_t Af[2][4];
            #pragma unroll
            for (int m = 0; m < 2; m++) lm4(Af[m], bu + aBase + aoff[m] + ksA);
            uint32_t Bf[6][4];
            #pragma unroll
            for (int t = 0; t < 6; t++) lm4t(Bf[t], bu + B_OFF + boff[t] + ksB);

            #pragma unroll
            for (int m = 0; m < 2; m++)
                #pragma unroll
                for (int t = 0; t < 6; t++) {
                    mma(acc[m][2*t],   Af[m], Bf[t][0], Bf[t][1]);
                    mma(acc[m][2*t+1], Af[m], Bf[t][2], Bf[t][3]);
                }
        }

        if (c + 1 < NCH) stchunk(smem + ((c + 1) & 1) * STAGE);
        __syncthreads();
    }

    // dump accumulators to smem (reuse stage buffers)
    float* D1s = (float*)smem;
    float* D2s = D1s + GT * CT;
    {
        float* Ds = mat ? D2s : D1s;
        const int dr = wg + (lane >> 2);
        const int dc = (lane & 3) * 2;
        #pragma unroll
        for (int m = 0; m < 2; m++)
            #pragma unroll
            for (int t = 0; t < 12; t++) {
                int r0 = dr + 16 * m, cc = dc + t * 8;
                Ds[r0 * CT + cc]         = acc[m][t][0];
                Ds[r0 * CT + cc + 1]     = acc[m][t][1];
                Ds[(r0 + 8) * CT + cc]   = acc[m][t][2];
                Ds[(r0 + 8) * CT + cc+1] = acc[m][t][3];
            }
    }
    __syncthreads();

    // epilogue: rotate by M1/M2, cross, add x
    float m1[9], m2[9];
    #pragma unroll
    for (int i = 0; i < 9; i++) { m1[i] = M1[i]; m2[i] = M2[i]; }

    #pragma unroll
    for (int p = tid; p < GT * NT; p += THREADS) {
        int g = p >> 5, nn = p & 31;
        float e10 = D1s[g * CT + 0 * NT + nn];
        float e11 = D1s[g * CT + 1 * NT + nn];
        float e12 = D1s[g * CT + 2 * NT + nn];
        float e20 = D2s[g * CT + 0 * NT + nn];
        float e21 = D2s[g * CT + 1 * NT + nn];
        float e22 = D2s[g * CT + 2 * NT + nn];
        float q0 = fmaf(m1[0], e10, fmaf(m1[1], e11, m1[2] * e12));
        float q1 = fmaf(m1[3], e10, fmaf(m1[4], e11, m1[5] * e12));
        float q2 = fmaf(m1[6], e10, fmaf(m1[7], e11, m1[8] * e12));
        float r0 = fmaf(m2[0], e20, fmaf(m2[1], e21, m2[2] * e22));
        float r1 = fmaf(m2[3], e20, fmaf(m2[4], e21, m2[5] * e22));
        float r2 = fmaf(m2[6], e20, fmaf(m2[7], e21, m2[8] * e22));
        float v0 = r1 * q2 - r2 * q1;   // cross(M2 d2, M1 d1)
        float v1 = r2 * q0 - r0 * q2;
        float v2 = r0 * q1 - r1 * q0;

        size_t base = ((size_t)(b * F_ + g0 + g) * 3) * NDIM + n0 + nn;
        out[base]            = x[base]            + v0;
        out[base + NDIM]     = x[base + NDIM]     + v1;
        out[base + 2 * NDIM] = x[base + 2 * NDIM] + v2;
    }
}

extern "C" void kernel_launch(void* const* d_in, const int* in_sizes, int n_in,
                              void* d_out, int out_size)
{
    const float* x  = (const float*)d_in[0];
    const float* M1 = (const float*)d_in[1];
    const float* M2 = (const float*)d_in[2];
    const float* W1 = (const float*)d_in[3];
    const float* W2 = (const float*)d_in[4];
    float* out = (float*)d_out;

    cudaFuncSetAttribute(lnlb_f16_kernel, cudaFuncAttributeMaxDynamicSharedMemorySize, SMEM_TOTAL);
    dim3 grid(NDIM / NT, F_ / GT, B_);   // (128, 2, 8)
    lnlb_f16_kernel<<<grid, THREADS, SMEM_TOTAL>>>(x, M1, M2, W1, W2, out);
}

// round 10
// speedup vs baseline: 1.2292x; 1.2292x over previous
#include <cuda_runtime.h>
#include <cuda_fp16.h>
#include <cstdint>

// LNLieBracketChannelMix via single-term fp16 mma.sync (fp32 accumulate).
// R10: back to R7 shape (64g x 96col CTA, 48 acc regs, 2 CTA/SM, 16 warps/SM)
//      but W tiles staged ONCE for all 8 chunks (64KB fp16 resident in smem);
//      per-chunk staging is B-only (3 LDG + 3 STS per thread, was 7+7).

#define B_    8
#define F_    256
#define NDIM  4096
#define COLS  12288
#define GT    64
#define NT    32
#define CT    96
#define KC    32
#define NCH   8
#define THREADS 256

#define A_STRIDE 528                 // 256 fp16 = 512B + 16B pad (row stride mod 128 = 16: conflict-free)
#define A_MAT    (GT * A_STRIDE)     // 33792 (one W matrix slice, all 256 f)
#define B_OFF    (2 * A_MAT)         // 67584
#define B_STRIDE 208                 // 96 fp16 = 192B + 16B pad
#define B_PART   (KC * B_STRIDE)     // 6656
#define SMEM_TOTAL (B_OFF + 2 * B_PART)  // 80896 (epilogue needs 49152, reused)

static __device__ __forceinline__ uint32_t s2u(const void* p) {
    uint32_t a;
    asm("{ .reg .u64 t; cvta.to.shared.u64 t, %1; cvt.u32.u64 %0, t; }" : "=r"(a) : "l"(p));
    return a;
}
static __device__ __forceinline__ void lm4(uint32_t* r, uint32_t a) {
    asm volatile("ldmatrix.sync.aligned.m8n8.x4.shared.b16 {%0,%1,%2,%3}, [%4];"
        : "=r"(r[0]), "=r"(r[1]), "=r"(r[2]), "=r"(r[3]) : "r"(a));
}
static __device__ __forceinline__ void lm4t(uint32_t* r, uint32_t a) {
    asm volatile("ldmatrix.sync.aligned.m8n8.x4.trans.shared.b16 {%0,%1,%2,%3}, [%4];"
        : "=r"(r[0]), "=r"(r[1]), "=r"(r[2]), "=r"(r[3]) : "r"(a));
}
static __device__ __forceinline__ void mma(float* d, const uint32_t* a, uint32_t b0, uint32_t b1) {
    asm volatile(
        "mma.sync.aligned.m16n8k16.row.col.f32.f16.f16.f32 "
        "{%0,%1,%2,%3}, {%4,%5,%6,%7}, {%8,%9}, {%0,%1,%2,%3};"
        : "+f"(d[0]), "+f"(d[1]), "+f"(d[2]), "+f"(d[3])
        : "r"(a[0]), "r"(a[1]), "r"(a[2]), "r"(a[3]), "r"(b0), "r"(b1));
}
static __device__ __forceinline__ uint2 cvt4h(float4 v) {
    __half2 a = __floats2half2_rn(v.x, v.y);
    __half2 b = __floats2half2_rn(v.z, v.w);
    uint2 r;
    r.x = *reinterpret_cast<uint32_t*>(&a);
    r.y = *reinterpret_cast<uint32_t*>(&b);
    return r;
}

__global__ __launch_bounds__(THREADS, 2)
void lnlb_f16_kernel(const float* __restrict__ x,
                     const float* __restrict__ M1,
                     const float* __restrict__ M2,
                     const float* __restrict__ W1,
                     const float* __restrict__ W2,
                     float* __restrict__ out)
{
    extern __shared__ char smem[];
    const uint32_t sb = s2u(smem);

    const int tid = threadIdx.x;
    const int warp = tid >> 5, lane = tid & 31;
    const int n0 = blockIdx.x * NT;
    const int g0 = blockIdx.y * GT;
    const int b  = blockIdx.z;
    const float* xb = x + (size_t)b * F_ * COLS;

    const int mat = warp >> 2;           // 0 -> W1/D1, 1 -> W2/D2
    const int q   = warp & 3;
    const int wg  = (q >> 1) * 32;       // g-strip (0/32)
    const int wc  = (q & 1) * 48;        // col-strip (0/48)

    float acc[2][6][4];
    #pragma unroll
    for (int m = 0; m < 2; m++)
        #pragma unroll
        for (int t = 0; t < 6; t++)
            #pragma unroll
            for (int j = 0; j < 4; j++) acc[m][t][j] = 0.f;

    const int lrow = lane & 15;
    const uint32_t lhA = (lane & 16) ? 16u : 0u;
    const uint32_t lhB = (lane & 16) ? 8u  : 0u;
    uint32_t aoff[2], boff[3];
    #pragma unroll
    for (int m = 0; m < 2; m++)
        aoff[m] = (uint32_t)(mat * A_MAT + (wg + 16 * m + lrow) * A_STRIDE) + lhA;
    #pragma unroll
    for (int t = 0; t < 3; t++) boff[t] = (uint32_t)(lrow * B_STRIDE + (wc + t * 16 + lhB) * 2);

    // ---- one-time A stage: both W slices [64 g x 256 f] -> fp16 smem ----
    // 8192 float4 total, 32 per thread
    #pragma unroll
    for (int j = 0; j < 32; j++) {
        int i = tid + j * THREADS;
        int t = i >> 12, r = i & 4095, g = r >> 6, fq = r & 63;
        float4 v = *(const float4*)((t ? W2 : W1) + (g0 + g) * F_ + fq * 4);
        *(uint2*)(smem + t * A_MAT + g * A_STRIDE + fq * 8) = cvt4h(v);
    }

    // ---- B register-pipelined staging ----
    float4 rb[3];
    auto ldB = [&](int c) {
        const int f0 = c * KC;
        #pragma unroll
        for (int j = 0; j < 3; j++) {          // 32 f x 24 col-quads
            int i = tid + j * THREADS;
            int f = i / 24, cq = i % 24;
            rb[j] = *(const float4*)(xb + (size_t)(f0 + f) * COLS + (cq >> 3) * NDIM + n0 + (cq & 7) * 4);
        }
    };
    auto stB = [&](char* buf) {
        #pragma unroll
        for (int j = 0; j < 3; j++) {
            int i = tid + j * THREADS;
            int f = i / 24, cq = i % 24;
            *(uint2*)(buf + f * B_STRIDE + cq * 8) = cvt4h(rb[j]);
        }
    };

    ldB(0);
    stB(smem + B_OFF);
    __syncthreads();

    for (int c = 0; c < NCH; ++c) {
        if (c + 1 < NCH) ldB(c + 1);           // B LDGs in flight over MMA block

        const uint32_t bu = sb + (uint32_t)(B_OFF + (c & 1) * B_PART);
        const uint32_t af = (uint32_t)(c * 64);   // f0 byte offset within A row (32 f * 2B)
        #pragma unroll
        for (int ks2 = 0; ks2 < 2; ++ks2) {
            const uint32_t ksA = af + ks2 * 32;
            const uint32_t ksB = ks2 * 16 * B_STRIDE;

            uint32_t Af[2][4];
            #pragma unroll
            for (int m = 0; m < 2; m++) lm4(Af[m], sb + aoff[m] + ksA);
            uint32_t Bf[3][4];
            #pragma unroll
            for (int t = 0; t < 3; t++) lm4t(Bf[t], bu + boff[t] + ksB);

            #pragma unroll
            for (int m = 0; m < 2; m++)
                #pragma unroll
                for (int t = 0; t < 3; t++) {
                    mma(acc[m][2*t],   Af[m], Bf[t][0], Bf[t][1]);
                    mma(acc[m][2*t+1], Af[m], Bf[t][2], Bf[t][3]);
                }
        }

        if (c + 1 < NCH) stB(smem + B_OFF + ((c + 1) & 1) * B_PART);
        __syncthreads();
    }

    // ---- dump accumulators to smem (reuse A region) ----
    float* D1s = (float*)smem;
    float* D2s = D1s + GT * CT;
    {
        float* Ds = mat ? D2s : D1s;
        const int dr = wg + (lane >> 2);
        const int dc = wc + (lane & 3) * 2;
        #pragma unroll
        for (int m = 0; m < 2; m++)
            #pragma unroll
            for (int t = 0; t < 6; t++) {
                int r0 = dr + 16 * m, cc = dc + t * 8;
                Ds[r0 * CT + cc]         = acc[m][t][0];
                Ds[r0 * CT + cc + 1]     = acc[m][t][1];
                Ds[(r0 + 8) * CT + cc]   = acc[m][t][2];
                Ds[(r0 + 8) * CT + cc+1] = acc[m][t][3];
            }
    }
    __syncthreads();

    // ---- epilogue: rotate by M1/M2, cross, add x ----
    float m1[9], m2[9];
    #pragma unroll
    for (int i = 0; i < 9; i++) { m1[i] = M1[i]; m2[i] = M2[i]; }

    #pragma unroll
    for (int p = tid; p < GT * NT; p += THREADS) {
        int g = p >> 5, nn = p & 31;
        float e10 = D1s[g * CT + 0 * NT + nn];
        float e11 = D1s[g * CT + 1 * NT + nn];
        float e12 = D1s[g * CT + 2 * NT + nn];
        float e20 = D2s[g * CT + 0 * NT + nn];
        float e21 = D2s[g * CT + 1 * NT + nn];
        float e22 = D2s[g * CT + 2 * NT + nn];
        float q0 = fmaf(m1[0], e10, fmaf(m1[1], e11, m1[2] * e12));
        float q1 = fmaf(m1[3], e10, fmaf(m1[4], e11, m1[5] * e12));
        float q2 = fmaf(m1[6], e10, fmaf(m1[7], e11, m1[8] * e12));
        float r0 = fmaf(m2[0], e20, fmaf(m2[1], e21, m2[2] * e22));
        float r1 = fmaf(m2[3], e20, fmaf(m2[4], e21, m2[5] * e22));
        float r2 = fmaf(m2[6], e20, fmaf(m2[7], e21, m2[8] * e22));
        float v0 = r1 * q2 - r2 * q1;   // cross(M2 d2, M1 d1)
        float v1 = r2 * q0 - r0 * q2;
        float v2 = r0 * q1 - r1 * q0;

        size_t base = ((size_t)(b * F_ + g0 + g) * 3) * NDIM + n0 + nn;
        out[base]            = x[base]            + v0;
        out[base + NDIM]     = x[base + NDIM]     + v1;
        out[base + 2 * NDIM] = x[base + 2 * NDIM] + v2;
    }
}

extern "C" void kernel_launch(void* const* d_in, const int* in_sizes, int n_in,
                              void* d_out, int out_size)
{
    const float* x  = (const float*)d_in[0];
    const float* M1 = (const float*)d_in[1];
    const float* M2 = (const float*)d_in[2];
    const float* W1 = (const float*)d_in[3];
    const float* W2 = (const float*)d_in[4];
    float* out = (float*)d_out;

    cudaFuncSetAttribute(lnlb_f16_kernel, cudaFuncAttributeMaxDynamicSharedMemorySize, SMEM_TOTAL);
    dim3 grid(NDIM / NT, F_ / GT, B_);   // (128, 4, 8)
    lnlb_f16_kernel<<<grid, THREADS, SMEM_TOTAL>>>(x, M1, M2, W1, W2, out);
}

// round 13
// speedup vs baseline: 1.2746x; 1.0369x over previous
#include <cuda_runtime.h>
#include <cuda_fp16.h>
#include <cstdint>

// LNLieBracketChannelMix via single-term fp16 mma.sync (fp32 accumulate).
// R13 = R10 + W pre-converted to fp16 global scratch (2us prepass); A staged
//       one-time with plain uint4 LDG+STS (NO cp.async — both container-death
//       rounds used cp.async from __device__ scratch; avoiding that path).

#define B_    8
#define F_    256
#define NDIM  4096
#define COLS  12288
#define GT    64
#define NT    32
#define CT    96
#define KC    32
#define NCH   8
#define THREADS 256

#define A_STRIDE 528                 // 256 fp16 = 512B + 16B pad (row stride mod 128B = 16B)
#define A_MAT    (GT * A_STRIDE)     // 33792
#define B_OFF    (2 * A_MAT)         // 67584
#define B_STRIDE 208                 // 96 fp16 = 192B + 16B pad
#define B_PART   (KC * B_STRIDE)     // 6656
#define SMEM_TOTAL (B_OFF + 2 * B_PART)  // 80896

// fp16 W scratch: [w1, w2], 256 KB total
__device__ __align__(256) __half g_wh[2][F_ * F_];

static __device__ __forceinline__ uint32_t s2u(const void* p) {
    uint32_t a;
    asm("{ .reg .u64 t; cvta.to.shared.u64 t, %1; cvt.u32.u64 %0, t; }" : "=r"(a) : "l"(p));
    return a;
}
static __device__ __forceinline__ void lm4(uint32_t* r, uint32_t a) {
    asm volatile("ldmatrix.sync.aligned.m8n8.x4.shared.b16 {%0,%1,%2,%3}, [%4];"
        : "=r"(r[0]), "=r"(r[1]), "=r"(r[2]), "=r"(r[3]) : "r"(a));
}
static __device__ __forceinline__ void lm4t(uint32_t* r, uint32_t a) {
    asm volatile("ldmatrix.sync.aligned.m8n8.x4.trans.shared.b16 {%0,%1,%2,%3}, [%4];"
        : "=r"(r[0]), "=r"(r[1]), "=r"(r[2]), "=r"(r[3]) : "r"(a));
}
static __device__ __forceinline__ void mma(float* d, const uint32_t* a, uint32_t b0, uint32_t b1) {
    asm volatile(
        "mma.sync.aligned.m16n8k16.row.col.f32.f16.f16.f32 "
        "{%0,%1,%2,%3}, {%4,%5,%6,%7}, {%8,%9}, {%0,%1,%2,%3};"
        : "+f"(d[0]), "+f"(d[1]), "+f"(d[2]), "+f"(d[3])
        : "r"(a[0]), "r"(a[1]), "r"(a[2]), "r"(a[3]), "r"(b0), "r"(b1));
}
static __device__ __forceinline__ uint2 cvt4h(float4 v) {
    __half2 a = __floats2half2_rn(v.x, v.y);
    __half2 b = __floats2half2_rn(v.z, v.w);
    uint2 r;
    r.x = *reinterpret_cast<uint32_t*>(&a);
    r.y = *reinterpret_cast<uint32_t*>(&b);
    return r;
}

__global__ __launch_bounds__(256) void cvt_w_kernel(const float* __restrict__ W1,
                                                    const float* __restrict__ W2) {
    int i = blockIdx.x * blockDim.x + threadIdx.x;   // float4 index, 0..16383
    if (i < F_ * F_ / 4) {
        ((uint2*)g_wh[0])[i] = cvt4h(((const float4*)W1)[i]);
        ((uint2*)g_wh[1])[i] = cvt4h(((const float4*)W2)[i]);
    }
}

__global__ __launch_bounds__(THREADS, 2)
void lnlb_f16_kernel(const float* __restrict__ x,
                     const float* __restrict__ M1,
                     const float* __restrict__ M2,
                     float* __restrict__ out)
{
    extern __shared__ char smem[];
    const uint32_t sb = s2u(smem);

    const int tid = threadIdx.x;
    const int warp = tid >> 5, lane = tid & 31;
    const int n0 = blockIdx.x * NT;
    const int g0 = blockIdx.y * GT;
    const int b  = blockIdx.z;
    const float* xb = x + (size_t)b * F_ * COLS;

    const int mat = warp >> 2;           // 0 -> W1/D1, 1 -> W2/D2
    const int q   = warp & 3;
    const int wg  = (q >> 1) * 32;       // g-strip (0/32)
    const int wc  = (q & 1) * 48;        // col-strip (0/48)

    float acc[2][6][4];
    #pragma unroll
    for (int m = 0; m < 2; m++)
        #pragma unroll
        for (int t = 0; t < 6; t++)
            #pragma unroll
            for (int j = 0; j < 4; j++) acc[m][t][j] = 0.f;

    const int lrow = lane & 15;
    const uint32_t lhA = (lane & 16) ? 16u : 0u;
    const uint32_t lhB = (lane & 16) ? 8u  : 0u;
    uint32_t aoff[2], boff[3];
    #pragma unroll
    for (int m = 0; m < 2; m++)
        aoff[m] = (uint32_t)(mat * A_MAT + (wg + 16 * m + lrow) * A_STRIDE) + lhA;
    #pragma unroll
    for (int t = 0; t < 3; t++) boff[t] = (uint32_t)(lrow * B_STRIDE + (wc + t * 16 + lhB) * 2);

    // ---- one-time A stage: copy fp16 W slices [2 x 64 g x 256 f] into smem ----
    // 4096 x 16B chunks, 16 per thread (plain LDG.128 + STS.128)
    #pragma unroll
    for (int j = 0; j < 16; j++) {
        int i = tid + j * THREADS;
        int t = i >> 11, r = i & 2047, g = r >> 5, fq = r & 31;
        uint4 v = *(const uint4*)(g_wh[t] + (g0 + g) * F_ + fq * 8);
        *(uint4*)(smem + t * A_MAT + g * A_STRIDE + fq * 16) = v;
    }

    // ---- B register-pipelined staging ----
    float4 rb[3];
    auto ldB = [&](int c) {
        const int f0 = c * KC;
        #pragma unroll
        for (int j = 0; j < 3; j++) {          // 32 f x 24 col-quads
            int i = tid + j * THREADS;
            int f = i / 24, cq = i % 24;
            rb[j] = *(const float4*)(xb + (size_t)(f0 + f) * COLS + (cq >> 3) * NDIM + n0 + (cq & 7) * 4);
        }
    };
    auto stB = [&](char* buf) {
        #pragma unroll
        for (int j = 0; j < 3; j++) {
            int i = tid + j * THREADS;
            int f = i / 24, cq = i % 24;
            *(uint2*)(buf + f * B_STRIDE + cq * 8) = cvt4h(rb[j]);
        }
    };

    ldB(0);
    stB(smem + B_OFF);
    __syncthreads();

    for (int c = 0; c < NCH; ++c) {
        if (c + 1 < NCH) ldB(c + 1);           // B LDGs in flight over MMA block

        const uint32_t bu = sb + (uint32_t)(B_OFF + (c & 1) * B_PART);
        const uint32_t af = (uint32_t)(c * 64);   // f0 byte offset within A row
        #pragma unroll
        for (int ks2 = 0; ks2 < 2; ++ks2) {
            const uint32_t ksA = af + ks2 * 32;
            const uint32_t ksB = ks2 * 16 * B_STRIDE;

            uint32_t Af[2][4];
            #pragma unroll
            for (int m = 0; m < 2; m++) lm4(Af[m], sb + aoff[m] + ksA);
            uint32_t Bf[3][4];
            #pragma unroll
            for (int t = 0; t < 3; t++) lm4t(Bf[t], bu + boff[t] + ksB);

            #pragma unroll
            for (int m = 0; m < 2; m++)
                #pragma unroll
                for (int t = 0; t < 3; t++) {
                    mma(acc[m][2*t],   Af[m], Bf[t][0], Bf[t][1]);
                    mma(acc[m][2*t+1], Af[m], Bf[t][2], Bf[t][3]);
                }
        }

        if (c + 1 < NCH) stB(smem + B_OFF + ((c + 1) & 1) * B_PART);
        __syncthreads();
    }

    // ---- dump accumulators to smem (reuse A region) ----
    float* D1s = (float*)smem;
    float* D2s = D1s + GT * CT;
    {
        float* Ds = mat ? D2s : D1s;
        const int dr = wg + (lane >> 2);
        const int dc = wc + (lane & 3) * 2;
        #pragma unroll
        for (int m = 0; m < 2; m++)
            #pragma unroll
            for (int t = 0; t < 6; t++) {
                int r0 = dr + 16 * m, cc = dc + t * 8;
                Ds[r0 * CT + cc]         = acc[m][t][0];
                Ds[r0 * CT + cc + 1]     = acc[m][t][1];
                Ds[(r0 + 8) * CT + cc]   = acc[m][t][2];
                Ds[(r0 + 8) * CT + cc+1] = acc[m][t][3];
            }
    }
    __syncthreads();

    // ---- epilogue: rotate by M1/M2, cross, add x ----
    float m1[9], m2[9];
    #pragma unroll
    for (int i = 0; i < 9; i++) { m1[i] = M1[i]; m2[i] = M2[i]; }

    #pragma unroll
    for (int p = tid; p < GT * NT; p += THREADS) {
        int g = p >> 5, nn = p & 31;
        float e10 = D1s[g * CT + 0 * NT + nn];
        float e11 = D1s[g * CT + 1 * NT + nn];
        float e12 = D1s[g * CT + 2 * NT + nn];
        float e20 = D2s[g * CT + 0 * NT + nn];
        float e21 = D2s[g * CT + 1 * NT + nn];
        float e22 = D2s[g * CT + 2 * NT + nn];
        float q0 = fmaf(m1[0], e10, fmaf(m1[1], e11, m1[2] * e12));
        float q1 = fmaf(m1[3], e10, fmaf(m1[4], e11, m1[5] * e12));
        float q2 = fmaf(m1[6], e10, fmaf(m1[7], e11, m1[8] * e12));
        float r0 = fmaf(m2[0], e20, fmaf(m2[1], e21, m2[2] * e22));
        float r1 = fmaf(m2[3], e20, fmaf(m2[4], e21, m2[5] * e22));
        float r2 = fmaf(m2[6], e20, fmaf(m2[7], e21, m2[8] * e22));
        float v0 = r1 * q2 - r2 * q1;   // cross(M2 d2, M1 d1)
        float v1 = r2 * q0 - r0 * q2;
        float v2 = r0 * q1 - r1 * q0;

        size_t base = ((size_t)(b * F_ + g0 + g) * 3) * NDIM + n0 + nn;
        out[base]            = x[base]            + v0;
        out[base + NDIM]     = x[base + NDIM]     + v1;
        out[base + 2 * NDIM] = x[base + 2 * NDIM] + v2;
    }
}

extern "C" void kernel_launch(void* const* d_in, const int* in_sizes, int n_in,
                              void* d_out, int out_size)
{
    const float* x  = (const float*)d_in[0];
    const float* M1 = (const float*)d_in[1];
    const float* M2 = (const float*)d_in[2];
    const float* W1 = (const float*)d_in[3];
    const float* W2 = (const float*)d_in[4];
    float* out = (float*)d_out;

    cvt_w_kernel<<<64, 256>>>(W1, W2);

    cudaFuncSetAttribute(lnlb_f16_kernel, cudaFuncAttributeMaxDynamicSharedMemorySize, SMEM_TOTAL);
    dim3 grid(NDIM / NT, F_ / GT, B_);   // (128, 4, 8)
    lnlb_f16_kernel<<<grid, THREADS, SMEM_TOTAL>>>(x, M1, M2, out);
}

// round 15
// speedup vs baseline: 1.4536x; 1.1405x over previous
#include <cuda_runtime.h>
#include <cuda_fp16.h>
#include <cstdint>

// LNLieBracketChannelMix via single-term fp16 mma.sync (fp32 accumulate).
// R14 = R13 + epilogue dump de-conflicted: D stride 96 -> 104 floats
//       (8-row STS pattern tiles all 32 banks; was 8-way conflicted on 4 banks)
//       and float2 dump stores (12 STS.64 vs 24 STS.32 per thread).

#define B_    8
#define F_    256
#define NDIM  4096
#define COLS  12288
#define GT    64
#define NT    32
#define CT    96
#define CTD   104                    // padded D row stride (floats): 104 mod 32 = 8
#define KC    32
#define NCH   8
#define THREADS 256

#define A_STRIDE 528                 // 256 fp16 = 512B + 16B pad
#define A_MAT    (GT * A_STRIDE)     // 33792
#define B_OFF    (2 * A_MAT)         // 67584
#define B_STRIDE 208                 // 96 fp16 = 192B + 16B pad
#define B_PART   (KC * B_STRIDE)     // 6656
#define SMEM_TOTAL (B_OFF + 2 * B_PART)  // 80896 (epilogue needs 2*64*104*4=53248, reused)

// fp16 W scratch: [w1, w2], 256 KB total
__device__ __align__(256) __half g_wh[2][F_ * F_];

static __device__ __forceinline__ uint32_t s2u(const void* p) {
    uint32_t a;
    asm("{ .reg .u64 t; cvta.to.shared.u64 t, %1; cvt.u32.u64 %0, t; }" : "=r"(a) : "l"(p));
    return a;
}
static __device__ __forceinline__ void lm4(uint32_t* r, uint32_t a) {
    asm volatile("ldmatrix.sync.aligned.m8n8.x4.shared.b16 {%0,%1,%2,%3}, [%4];"
        : "=r"(r[0]), "=r"(r[1]), "=r"(r[2]), "=r"(r[3]) : "r"(a));
}
static __device__ __forceinline__ void lm4t(uint32_t* r, uint32_t a) {
    asm volatile("ldmatrix.sync.aligned.m8n8.x4.trans.shared.b16 {%0,%1,%2,%3}, [%4];"
        : "=r"(r[0]), "=r"(r[1]), "=r"(r[2]), "=r"(r[3]) : "r"(a));
}
static __device__ __forceinline__ void mma(float* d, const uint32_t* a, uint32_t b0, uint32_t b1) {
    asm volatile(
        "mma.sync.aligned.m16n8k16.row.col.f32.f16.f16.f32 "
        "{%0,%1,%2,%3}, {%4,%5,%6,%7}, {%8,%9}, {%0,%1,%2,%3};"
        : "+f"(d[0]), "+f"(d[1]), "+f"(d[2]), "+f"(d[3])
        : "r"(a[0]), "r"(a[1]), "r"(a[2]), "r"(a[3]), "r"(b0), "r"(b1));
}
static __device__ __forceinline__ uint2 cvt4h(float4 v) {
    __half2 a = __floats2half2_rn(v.x, v.y);
    __half2 b = __floats2half2_rn(v.z, v.w);
    uint2 r;
    r.x = *reinterpret_cast<uint32_t*>(&a);
    r.y = *reinterpret_cast<uint32_t*>(&b);
    return r;
}

__global__ __launch_bounds__(256) void cvt_w_kernel(const float* __restrict__ W1,
                                                    const float* __restrict__ W2) {
    int i = blockIdx.x * blockDim.x + threadIdx.x;   // float4 index, 0..16383
    if (i < F_ * F_ / 4) {
        ((uint2*)g_wh[0])[i] = cvt4h(((const float4*)W1)[i]);
        ((uint2*)g_wh[1])[i] = cvt4h(((const float4*)W2)[i]);
    }
}

__global__ __launch_bounds__(THREADS, 2)
void lnlb_f16_kernel(const float* __restrict__ x,
                     const float* __restrict__ M1,
                     const float* __restrict__ M2,
                     float* __restrict__ out)
{
    extern __shared__ char smem[];
    const uint32_t sb = s2u(smem);

    const int tid = threadIdx.x;
    const int warp = tid >> 5, lane = tid & 31;
    const int n0 = blockIdx.x * NT;
    const int g0 = blockIdx.y * GT;
    const int b  = blockIdx.z;
    const float* xb = x + (size_t)b * F_ * COLS;

    const int mat = warp >> 2;           // 0 -> W1/D1, 1 -> W2/D2
    const int q   = warp & 3;
    const int wg  = (q >> 1) * 32;       // g-strip (0/32)
    const int wc  = (q & 1) * 48;        // col-strip (0/48)

    float acc[2][6][4];
    #pragma unroll
    for (int m = 0; m < 2; m++)
        #pragma unroll
        for (int t = 0; t < 6; t++)
            #pragma unroll
            for (int j = 0; j < 4; j++) acc[m][t][j] = 0.f;

    const int lrow = lane & 15;
    const uint32_t lhA = (lane & 16) ? 16u : 0u;
    const uint32_t lhB = (lane & 16) ? 8u  : 0u;
    uint32_t aoff[2], boff[3];
    #pragma unroll
    for (int m = 0; m < 2; m++)
        aoff[m] = (uint32_t)(mat * A_MAT + (wg + 16 * m + lrow) * A_STRIDE) + lhA;
    #pragma unroll
    for (int t = 0; t < 3; t++) boff[t] = (uint32_t)(lrow * B_STRIDE + (wc + t * 16 + lhB) * 2);

    // ---- one-time A stage: copy fp16 W slices [2 x 64 g x 256 f] into smem ----
    #pragma unroll
    for (int j = 0; j < 16; j++) {
        int i = tid + j * THREADS;
        int t = i >> 11, r = i & 2047, g = r >> 5, fq = r & 31;
        uint4 v = *(const uint4*)(g_wh[t] + (g0 + g) * F_ + fq * 8);
        *(uint4*)(smem + t * A_MAT + g * A_STRIDE + fq * 16) = v;
    }

    // ---- B register-pipelined staging ----
    float4 rb[3];
    auto ldB = [&](int c) {
        const int f0 = c * KC;
        #pragma unroll
        for (int j = 0; j < 3; j++) {          // 32 f x 24 col-quads
            int i = tid + j * THREADS;
            int f = i / 24, cq = i % 24;
            rb[j] = *(const float4*)(xb + (size_t)(f0 + f) * COLS + (cq >> 3) * NDIM + n0 + (cq & 7) * 4);
        }
    };
    auto stB = [&](char* buf) {
        #pragma unroll
        for (int j = 0; j < 3; j++) {
            int i = tid + j * THREADS;
            int f = i / 24, cq = i % 24;
            *(uint2*)(buf + f * B_STRIDE + cq * 8) = cvt4h(rb[j]);
        }
    };

    ldB(0);
    stB(smem + B_OFF);
    __syncthreads();

    for (int c = 0; c < NCH; ++c) {
        if (c + 1 < NCH) ldB(c + 1);           // B LDGs in flight over MMA block

        const uint32_t bu = sb + (uint32_t)(B_OFF + (c & 1) * B_PART);
        const uint32_t af = (uint32_t)(c * 64);   // f0 byte offset within A row
        #pragma unroll
        for (int ks2 = 0; ks2 < 2; ++ks2) {
            const uint32_t ksA = af + ks2 * 32;
            const uint32_t ksB = ks2 * 16 * B_STRIDE;

            uint32_t Af[2][4];
            #pragma unroll
            for (int m = 0; m < 2; m++) lm4(Af[m], sb + aoff[m] + ksA);
            uint32_t Bf[3][4];
            #pragma unroll
            for (int t = 0; t < 3; t++) lm4t(Bf[t], bu + boff[t] + ksB);

            #pragma unroll
            for (int m = 0; m < 2; m++)
                #pragma unroll
                for (int t = 0; t < 3; t++) {
                    mma(acc[m][2*t],   Af[m], Bf[t][0], Bf[t][1]);
                    mma(acc[m][2*t+1], Af[m], Bf[t][2], Bf[t][3]);
                }
        }

        if (c + 1 < NCH) stB(smem + B_OFF + ((c + 1) & 1) * B_PART);
        __syncthreads();
    }

    // ---- dump accumulators to smem (padded stride, float2, conflict-free) ----
    float* D1s = (float*)smem;
    float* D2s = D1s + GT * CTD;
    {
        float* Ds = mat ? D2s : D1s;
        const int dr = wg + (lane >> 2);
        const int dc = wc + (lane & 3) * 2;
        #pragma unroll
        for (int m = 0; m < 2; m++)
            #pragma unroll
            for (int t = 0; t < 6; t++) {
                int r0 = dr + 16 * m, cc = dc + t * 8;
                float2 lo = { acc[m][t][0], acc[m][t][1] };
                float2 hi = { acc[m][t][2], acc[m][t][3] };
                *(float2*)&Ds[r0 * CTD + cc]       = lo;
                *(float2*)&Ds[(r0 + 8) * CTD + cc] = hi;
            }
    }
    __syncthreads();

    // ---- epilogue: rotate by M1/M2, cross, add x ----
    float m1[9], m2[9];
    #pragma unroll
    for (int i = 0; i < 9; i++) { m1[i] = M1[i]; m2[i] = M2[i]; }

    #pragma unroll
    for (int p = tid; p < GT * NT; p += THREADS) {
        int g = p >> 5, nn = p & 31;
        float e10 = D1s[g * CTD + 0 * NT + nn];
        float e11 = D1s[g * CTD + 1 * NT + nn];
        float e12 = D1s[g * CTD + 2 * NT + nn];
        float e20 = D2s[g * CTD + 0 * NT + nn];
        float e21 = D2s[g * CTD + 1 * NT + nn];
        float e22 = D2s[g * CTD + 2 * NT + nn];
        float q0 = fmaf(m1[0], e10, fmaf(m1[1], e11, m1[2] * e12));
        float q1 = fmaf(m1[3], e10, fmaf(m1[4], e11, m1[5] * e12));
        float q2 = fmaf(m1[6], e10, fmaf(m1[7], e11, m1[8] * e12));
        float r0 = fmaf(m2[0], e20, fmaf(m2[1], e21, m2[2] * e22));
        float r1 = fmaf(m2[3], e20, fmaf(m2[4], e21, m2[5] * e22));
        float r2 = fmaf(m2[6], e20, fmaf(m2[7], e21, m2[8] * e22));
        float v0 = r1 * q2 - r2 * q1;   // cross(M2 d2, M1 d1)
        float v1 = r2 * q0 - r0 * q2;
        float v2 = r0 * q1 - r1 * q0;

        size_t base = ((size_t)(b * F_ + g0 + g) * 3) * NDIM + n0 + nn;
        out[base]            = x[base]            + v0;
        out[base + NDIM]     = x[base + NDIM]     + v1;
        out[base + 2 * NDIM] = x[base + 2 * NDIM] + v2;
    }
}

extern "C" void kernel_launch(void* const* d_in, const int* in_sizes, int n_in,
                              void* d_out, int out_size)
{
    const float* x  = (const float*)d_in[0];
    const float* M1 = (const float*)d_in[1];
    const float* M2 = (const float*)d_in[2];
    const float* W1 = (const float*)d_in[3];
    const float* W2 = (const float*)d_in[4];
    float* out = (float*)d_out;

    cvt_w_kernel<<<64, 256>>>(W1, W2);

    cudaFuncSetAttribute(lnlb_f16_kernel, cudaFuncAttributeMaxDynamicSharedMemorySize, SMEM_TOTAL);
    dim3 grid(NDIM / NT, F_ / GT, B_);   // (128, 4, 8)
    lnlb_f16_kernel<<<grid, THREADS, SMEM_TOTAL>>>(x, M1, M2, out);
}